// round 2
// baseline (speedup 1.0000x reference)
#include <cuda_runtime.h>
#include <math.h>

// Problem constants (shapes fixed by the dataset)
#define NN 50000
#define EE 800000
#define IN_DIM 128
#define HID 512
#define H_DIM 128
#define OUT_DIM 64

// ---------------- scratch (device globals; no allocs allowed) ----------------
__device__ __align__(16) float g_h1[NN * HID];        // 102.4 MB
__device__ __align__(16) float g_logits[NN * OUT_DIM];
__device__ __align__(16) float g_lp[NN * OUT_DIM];
__device__ __align__(16) float g_x0[NN * H_DIM];
__device__ __align__(16) float g_agg[NN * H_DIM];
__device__ __align__(16) float g_hbuf[NN * H_DIM];
__device__ __align__(16) float g_ew[EE];
__device__ __align__(16) float g_ewn[EE];
__device__ float g_deg[NN];
__device__ float g_dinv[NN];
__device__ __align__(16) float g_P[OUT_DIM * OUT_DIM];
__device__ __align__(16) float g_Weff[2][H_DIM * H_DIM];
__device__ double g_stats[2];
__device__ float g_mean, g_scale;

// ---------------- prep: P = relu(2*parsing[0]); Weff = (1-b)I + b*W1; zero stats
__global__ void prep_k(const float* __restrict__ parsing,
                       const float* __restrict__ conv_w1) {
    int t = blockIdx.x * blockDim.x + threadIdx.x;
    if (t == 0) { g_stats[0] = 0.0; g_stats[1] = 0.0; }
    if (t < OUT_DIM * OUT_DIM) {
        g_P[t] = fmaxf(2.0f * parsing[t], 0.0f);
    }
    if (t < H_DIM * H_DIM) {
        int i = t / H_DIM, j = t % H_DIM;
        const float b0 = 0.6931471805599453f;   // log(1/1 + 1)
        const float b1 = 0.40546510810816444f;  // log(1/2 + 1)
        float i0 = (i == j) ? (1.0f - b0) : 0.0f;
        float i1 = (i == j) ? (1.0f - b1) : 0.0f;
        g_Weff[0][t] = b0 * conv_w1[t] + i0;
        g_Weff[1][t] = b1 * conv_w1[H_DIM * H_DIM + t] + i1;
    }
}

// ---------------- fp32 SGEMM: C = act(A[M,K] @ B[K,Ncol] + bias) -------------
// BM=128, BN=64, BK=16, 256 threads, 8x4 micro-tile per thread.
// Requires: K % 16 == 0, Ncol % 4 == 0, A/B/C 16B-aligned (true for all calls).
#define BM 128
#define BN 64
#define BK 16

template <bool RELU, bool BIAS>
__global__ __launch_bounds__(256) void sgemm_k(const float* __restrict__ A,
                                               const float* __restrict__ B,
                                               const float* __restrict__ bias,
                                               float* __restrict__ C,
                                               int M, int K, int Ncol) {
    __shared__ float As[BK][BM + 4];  // pad: scalar scatter stores stay conflict-free
    __shared__ float Bs[BK][BN];

    const int tid = threadIdx.x;
    const int tx = tid & 15;          // 0..15 -> col group (4 cols)
    const int ty = tid >> 4;          // 0..15 -> row group (8 rows)
    const int rowBase = blockIdx.x * BM;
    const int colBase = blockIdx.y * BN;

    // A tile load mapping: 128 rows x 16 k = 512 float4; 2 float4/thread
    const int aRow = tid & 127;             // 0..127
    const int aQ0  = (tid >> 7) << 1;       // 0 or 2 -> k-quad index (this + next)

    // B tile load mapping: 16 rows x 64 cols = 256 float4; 1/thread
    const int bRow = tid >> 4;              // 0..15 (k)
    const int bCol = (tid & 15) << 2;       // 0,4,...,60

    float acc[8][4];
#pragma unroll
    for (int m = 0; m < 8; m++)
#pragma unroll
        for (int n = 0; n < 4; n++) acc[m][n] = 0.0f;

    for (int k0 = 0; k0 < K; k0 += BK) {
        // load A (transposed into smem: As[k][m])
#pragma unroll
        for (int q = 0; q < 2; q++) {
            int kq = (aQ0 + q) << 2;        // 0,4,8,12
            int r = rowBase + aRow;
            float4 v = make_float4(0.f, 0.f, 0.f, 0.f);
            if (r < M) v = *(const float4*)&A[(size_t)r * K + k0 + kq];
            As[kq + 0][aRow] = v.x;
            As[kq + 1][aRow] = v.y;
            As[kq + 2][aRow] = v.z;
            As[kq + 3][aRow] = v.w;
        }
        // load B
        *(float4*)&Bs[bRow][bCol] =
            *(const float4*)&B[(size_t)(k0 + bRow) * Ncol + colBase + bCol];
        __syncthreads();

#pragma unroll
        for (int k = 0; k < BK; k++) {
            float4 ra0 = *(const float4*)&As[k][ty * 8];
            float4 ra1 = *(const float4*)&As[k][ty * 8 + 4];
            float4 rb  = *(const float4*)&Bs[k][tx * 4];
            float a[8] = {ra0.x, ra0.y, ra0.z, ra0.w, ra1.x, ra1.y, ra1.z, ra1.w};
            float b[4] = {rb.x, rb.y, rb.z, rb.w};
#pragma unroll
            for (int m = 0; m < 8; m++)
#pragma unroll
                for (int n = 0; n < 4; n++) acc[m][n] += a[m] * b[n];
        }
        __syncthreads();
    }

    float bv[4];
#pragma unroll
    for (int n = 0; n < 4; n++) bv[n] = BIAS ? bias[colBase + tx * 4 + n] : 0.0f;

#pragma unroll
    for (int m = 0; m < 8; m++) {
        int r = rowBase + ty * 8 + m;
        if (r >= M) continue;
        float4 o;
        float* po = (float*)&o;
#pragma unroll
        for (int n = 0; n < 4; n++) {
            float v = acc[m][n] + bv[n];
            if (RELU) v = fmaxf(v, 0.0f);
            po[n] = v;
        }
        *(float4*)&C[(size_t)r * Ncol + colBase + tx * 4] = o;
    }
}

// ---------------- edge dot + double-precision sum / sumsq --------------------
__global__ void edge_dot_k(const int* __restrict__ row, const int* __restrict__ col,
                           const float* __restrict__ logits,
                           const float* __restrict__ lp, int E) {
    int e = blockIdx.x * blockDim.x + threadIdx.x;
    float s = 0.0f;
    if (e < E) {
        const float4* a = (const float4*)(logits + (size_t)row[e] * OUT_DIM);
        const float4* b = (const float4*)(lp + (size_t)col[e] * OUT_DIM);
#pragma unroll
        for (int i = 0; i < OUT_DIM / 4; i++) {
            float4 fa = a[i], fb = b[i];
            s += fa.x * fb.x + fa.y * fb.y + fa.z * fb.z + fa.w * fb.w;
        }
        g_ew[e] = s;
    }
    double ds = (e < E) ? (double)s : 0.0;
    double dss = ds * ds;
#pragma unroll
    for (int o = 16; o > 0; o >>= 1) {
        ds += __shfl_down_sync(0xffffffffu, ds, o);
        dss += __shfl_down_sync(0xffffffffu, dss, o);
    }
    __shared__ double sh0[8], sh1[8];
    int w = threadIdx.x >> 5, l = threadIdx.x & 31;
    if (l == 0) { sh0[w] = ds; sh1[w] = dss; }
    __syncthreads();
    if (threadIdx.x == 0) {
        double t0 = 0, t1 = 0;
        int nw = blockDim.x >> 5;
        for (int i = 0; i < nw; i++) { t0 += sh0[i]; t1 += sh1[i]; }
        atomicAdd(&g_stats[0], t0);
        atomicAdd(&g_stats[1], t1);
    }
}

__global__ void finalize_stats_k(int E) {
    double sum = g_stats[0], sumsq = g_stats[1];
    double mean = sum / (double)E;
    double var = (sumsq - sum * sum / (double)E) / (double)(E - 1);
    g_mean = (float)mean;
    g_scale = (float)sqrt(1e-4 / var);
}

__global__ void deg_init_k(int N) {
    int i = blockIdx.x * blockDim.x + threadIdx.x;
    if (i < N) g_deg[i] = 1.0f;   // self-loop weight
}

__global__ void ewn_deg_k(const int* __restrict__ col, int E) {
    int e = blockIdx.x * blockDim.x + threadIdx.x;
    if (e < E) {
        float v = (g_ew[e] - g_mean) * g_scale + 1.0f;
        g_ewn[e] = v;
        atomicAdd(&g_deg[col[e]], v);
    }
}

__global__ void dinv_k(int N) {
    int i = blockIdx.x * blockDim.x + threadIdx.x;
    if (i < N) {
        float d = g_deg[i];
        g_dinv[i] = (d > 0.0f) ? rsqrtf(d) : 0.0f;
    }
}

// agg[i,:] = dinv[i]^2 * hin[i,:]   (self-loop contribution), float4-wide
__global__ void agg_init_k(const float* __restrict__ hin, int N) {
    int i = blockIdx.x * blockDim.x + threadIdx.x;  // over N*32 float4s
    if (i >= N * (H_DIM / 4)) return;
    int node = i / (H_DIM / 4);
    float d = g_dinv[node];
    float c = d * d;
    float4 h = ((const float4*)hin)[i];
    ((float4*)g_agg)[i] = make_float4(c * h.x, c * h.y, c * h.z, c * h.w);
}

// one warp per edge; vector red.global.add (sm_90+) -> 32 reds/edge not 128
__global__ __launch_bounds__(256) void scatter_k(const int* __restrict__ row,
                                                 const int* __restrict__ col,
                                                 const float* __restrict__ hin,
                                                 int E) {
    int warp = (blockIdx.x * blockDim.x + threadIdx.x) >> 5;
    int lane = threadIdx.x & 31;
    if (warp >= E) return;
    int r = row[warp];
    int c = col[warp];
    float coef = g_dinv[r] * g_ewn[warp] * g_dinv[c];
    float4 h = *(const float4*)(hin + (size_t)r * H_DIM + lane * 4);
    float* dst = g_agg + (size_t)c * H_DIM + lane * 4;
    asm volatile("red.global.add.v4.f32 [%0], {%1,%2,%3,%4};" ::"l"(dst),
                 "f"(coef * h.x), "f"(coef * h.y), "f"(coef * h.z),
                 "f"(coef * h.w)
                 : "memory");
}

// -----------------------------------------------------------------------------
extern "C" void kernel_launch(void* const* d_in, const int* in_sizes, int n_in,
                              void* d_out, int out_size) {
    const float* x        = (const float*)d_in[0];
    const int*   eidx     = (const int*)d_in[1];
    const float* mlp_w1   = (const float*)d_in[2];
    const float* mlp_b1   = (const float*)d_in[3];
    const float* mlp_w2   = (const float*)d_in[4];
    const float* mlp_b2   = (const float*)d_in[5];
    const float* mlp_w3   = (const float*)d_in[6];
    const float* mlp_b3   = (const float*)d_in[7];
    const float* parsing  = (const float*)d_in[8];
    const float* lin0_w   = (const float*)d_in[9];
    const float* lin0_b   = (const float*)d_in[10];
    const float* lin1_w   = (const float*)d_in[11];
    const float* lin1_b   = (const float*)d_in[12];
    const float* conv_w1  = (const float*)d_in[13];
    // conv_w2 (d_in[14]) is dead: alpha == 0 kills all x0a terms.

    const int N = in_sizes[0] / IN_DIM;
    const int E = in_sizes[1] / 2;
    const int* erow = eidx;
    const int* ecol = eidx + E;

    float* out = (float*)d_out;

    // resolve scratch addresses (host-side symbol query; not a stream op)
    float *p_h1, *p_logits, *p_lp, *p_x0, *p_agg, *p_hbuf, *p_P, *p_Weff;
    cudaGetSymbolAddress((void**)&p_h1, g_h1);
    cudaGetSymbolAddress((void**)&p_logits, g_logits);
    cudaGetSymbolAddress((void**)&p_lp, g_lp);
    cudaGetSymbolAddress((void**)&p_x0, g_x0);
    cudaGetSymbolAddress((void**)&p_agg, g_agg);
    cudaGetSymbolAddress((void**)&p_hbuf, g_hbuf);
    cudaGetSymbolAddress((void**)&p_P, g_P);
    cudaGetSymbolAddress((void**)&p_Weff, g_Weff);

    const int MB = (N + BM - 1) / BM;  // 391 row blocks

    // 0) prep
    prep_k<<<64, 256>>>(parsing, conv_w1);

    // 1) MLP: h1 = relu(x@w1+b1); h2 = relu(h1@w2+b2) (g_lp reused as h2 tmp);
    //    logits = h2@w3+b3; lp = logits@P
    sgemm_k<true, true><<<dim3(MB, HID / BN), 256>>>(x, mlp_w1, mlp_b1, p_h1, N, IN_DIM, HID);
    sgemm_k<true, true><<<dim3(MB, 1), 256>>>(p_h1, mlp_w2, mlp_b2, p_lp, N, HID, OUT_DIM);
    sgemm_k<false, true><<<dim3(MB, 1), 256>>>(p_lp, mlp_w3, mlp_b3, p_logits, N, OUT_DIM, OUT_DIM);
    sgemm_k<false, false><<<dim3(MB, 1), 256>>>(p_logits, p_P, nullptr, p_lp, N, OUT_DIM, OUT_DIM);

    // 2) x0 = relu(x@lin0+b0)
    sgemm_k<true, true><<<dim3(MB, H_DIM / BN), 256>>>(x, lin0_w, lin0_b, p_x0, N, IN_DIM, H_DIM);

    // 3) edge weights + standardization
    edge_dot_k<<<(E + 255) / 256, 256>>>(erow, ecol, p_logits, p_lp, E);
    finalize_stats_k<<<1, 1>>>(E);
    deg_init_k<<<(N + 255) / 256, 256>>>(N);
    ewn_deg_k<<<(E + 255) / 256, 256>>>(ecol, E);
    dinv_k<<<(N + 255) / 256, 256>>>(N);

    // 4) GCN2 layers (alpha=0 -> out = relu(agg @ Weff[ln]))
    const float* hin = p_x0;
    float* hout = p_hbuf;
    for (int ln = 0; ln < 2; ln++) {
        int nvec = N * (H_DIM / 4);
        agg_init_k<<<(nvec + 255) / 256, 256>>>(hin, N);
        scatter_k<<<(E * 32 + 255) / 256, 256>>>(erow, ecol, hin, E);
        sgemm_k<true, false><<<dim3(MB, H_DIM / BN), 256>>>(
            p_agg, p_Weff + ln * H_DIM * H_DIM, nullptr, hout, N, H_DIM, H_DIM);
        const float* t = hin;
        hin = hout;
        hout = (ln == 0) ? p_x0 : (float*)t;  // ping-pong (x0 dead after layer 0)
    }

    // 5) out = hcur @ lin1 + b  (no relu)
    sgemm_k<false, true><<<dim3(MB, 1), 256>>>(hin, lin1_w, lin1_b, out, N, H_DIM, OUT_DIM);
}

// round 6
// speedup vs baseline: 1.0099x; 1.0099x over previous
#include <cuda_runtime.h>
#include <math.h>

// Problem constants (shapes fixed by the dataset)
#define NN 50000
#define EE 800000
#define IN_DIM 128
#define HID 512
#define H_DIM 128
#define OUT_DIM 64

// ---------------- scratch (device globals; no allocs allowed) ----------------
__device__ __align__(16) float g_h1[NN * HID];        // 102.4 MB
__device__ __align__(16) float g_llp[NN * 128];       // [logits | logits@P] per node
__device__ __align__(16) float g_lp[NN * OUT_DIM];    // h2 temp
__device__ __align__(16) float g_x0[NN * H_DIM];
__device__ __align__(16) float g_agg[NN * H_DIM];
__device__ __align__(16) float g_hbuf[NN * H_DIM];
__device__ __align__(16) float g_ew[EE];
__device__ __align__(16) float g_ewn[EE];
__device__ float g_deg[NN];
__device__ float g_dinv[NN];
__device__ __align__(16) float g_P[OUT_DIM * OUT_DIM];
__device__ __align__(16) float g_Weff[2][H_DIM * H_DIM];
__device__ __align__(16) float g_Wcat[OUT_DIM * 128]; // [w3 | w3@P]
__device__ __align__(16) float g_bcat[128];           // [b3 | b3@P]
__device__ double g_stats[2];
__device__ float g_mean, g_scale;

// ---------------- packed f32x2 helpers (sm_100+) -----------------------------
typedef unsigned long long ull;
__device__ __forceinline__ ull fma2(ull a, ull b, ull c) {
    ull d;
    asm("fma.rn.f32x2 %0, %1, %2, %3;" : "=l"(d) : "l"(a), "l"(b), "l"(c));
    return d;
}
__device__ __forceinline__ ull dup2(float x) {
    ull d;
    asm("mov.b64 %0, {%1, %1};" : "=l"(d) : "f"(x));
    return d;
}

// ---------------- prep: P = relu(2*parsing[0]); Weff = (1-b)I + b*W1 ---------
__global__ void prep_k(const float* __restrict__ parsing,
                       const float* __restrict__ conv_w1) {
    int t = blockIdx.x * blockDim.x + threadIdx.x;
    if (t == 0) { g_stats[0] = 0.0; g_stats[1] = 0.0; }
    if (t < OUT_DIM * OUT_DIM) {
        g_P[t] = fmaxf(2.0f * parsing[t], 0.0f);
    }
    if (t < H_DIM * H_DIM) {
        int i = t / H_DIM, j = t % H_DIM;
        const float b0 = 0.6931471805599453f;   // log(1/1 + 1)
        const float b1 = 0.40546510810816444f;  // log(1/2 + 1)
        float i0 = (i == j) ? (1.0f - b0) : 0.0f;
        float i1 = (i == j) ? (1.0f - b1) : 0.0f;
        g_Weff[0][t] = b0 * conv_w1[t] + i0;
        g_Weff[1][t] = b1 * conv_w1[H_DIM * H_DIM + t] + i1;
    }
}

// prep2: Wcat = [w3 | w3@P], bcat = [b3 | b3@P]  (single block, after prep_k)
__global__ void prep2_k(const float* __restrict__ w3, const float* __restrict__ b3) {
    __shared__ float sw[64 * 64], sp[64 * 64];
    int tid = threadIdx.x;
    for (int i = tid; i < 4096; i += blockDim.x) { sw[i] = w3[i]; sp[i] = g_P[i]; }
    __syncthreads();
    for (int i = tid; i < 4096; i += blockDim.x) {
        int k = i >> 6, n = i & 63;
        float s = 0.0f;
#pragma unroll 8
        for (int j = 0; j < 64; j++) s += sw[k * 64 + j] * sp[j * 64 + n];
        g_Wcat[k * 128 + n] = sw[i];
        g_Wcat[k * 128 + 64 + n] = s;
    }
    if (tid < 64) {
        float s = 0.0f;
        for (int j = 0; j < 64; j++) s += b3[j] * sp[j * 64 + tid];
        g_bcat[tid] = b3[tid];
        g_bcat[64 + tid] = s;
    }
}

// ---------------- fp32 SGEMM via packed FFMA2: C = act(A@B + bias) -----------
// BM=128, BN=64, BK=16, 256 threads, 8x4 micro-tile per thread.
// acc pairs packed along m (float4 A-loads give (m,m+1) 64-bit halves for free).
// Requires: K % 16 == 0, Ncol % 4 == 0, A/B/C 16B-aligned (true for all calls).
#define BM 128
#define BN 64
#define BK 16

template <bool RELU, bool BIAS>
__global__ __launch_bounds__(256) void sgemm_k(const float* __restrict__ A,
                                               const float* __restrict__ B,
                                               const float* __restrict__ bias,
                                               float* __restrict__ C,
                                               int M, int K, int Ncol) {
    __shared__ float As[BK][BM + 4];  // 132: 16B-aligned rows, conflict-free stores
    __shared__ float Bs[BK][BN];

    const int tid = threadIdx.x;
    const int tx = tid & 15;          // col group (4 cols)
    const int ty = tid >> 4;          // row group (8 rows)
    const int rowBase = blockIdx.x * BM;
    const int colBase = blockIdx.y * BN;

    // A tile load: 128 rows x 16 k = 512 float4; 2 float4/thread
    const int aRow = tid & 127;
    const int aQ0  = (tid >> 7) << 1;

    // B tile load: 16 rows x 64 cols = 256 float4; 1/thread
    const int bRow = tid >> 4;
    const int bCol = (tid & 15) << 2;

    ull acc2[4][4];                   // [m-pair][n], each holds rows (2mi,2mi+1)
#pragma unroll
    for (int mi = 0; mi < 4; mi++)
#pragma unroll
        for (int n = 0; n < 4; n++) acc2[mi][n] = 0ULL;

    for (int k0 = 0; k0 < K; k0 += BK) {
#pragma unroll
        for (int q = 0; q < 2; q++) {
            int kq = (aQ0 + q) << 2;
            int r = rowBase + aRow;
            float4 v = make_float4(0.f, 0.f, 0.f, 0.f);
            if (r < M) v = *(const float4*)&A[(size_t)r * K + k0 + kq];
            As[kq + 0][aRow] = v.x;
            As[kq + 1][aRow] = v.y;
            As[kq + 2][aRow] = v.z;
            As[kq + 3][aRow] = v.w;
        }
        *(float4*)&Bs[bRow][bCol] =
            *(const float4*)&B[(size_t)(k0 + bRow) * Ncol + colBase + bCol];
        __syncthreads();

#pragma unroll
        for (int k = 0; k < BK; k++) {
            float4 ra0 = *(const float4*)&As[k][ty * 8];      // m0..m3
            float4 ra1 = *(const float4*)&As[k][ty * 8 + 4];  // m4..m7
            float4 rb  = *(const float4*)&Bs[k][tx * 4];
            ull a2[4];
            a2[0] = ((const ull*)&ra0)[0];   // (m0,m1)
            a2[1] = ((const ull*)&ra0)[1];   // (m2,m3)
            a2[2] = ((const ull*)&ra1)[0];   // (m4,m5)
            a2[3] = ((const ull*)&ra1)[1];   // (m6,m7)
            ull b2[4] = {dup2(rb.x), dup2(rb.y), dup2(rb.z), dup2(rb.w)};
#pragma unroll
            for (int mi = 0; mi < 4; mi++)
#pragma unroll
                for (int n = 0; n < 4; n++)
                    acc2[mi][n] = fma2(a2[mi], b2[n], acc2[mi][n]);
        }
        __syncthreads();
    }

    float bv[4];
#pragma unroll
    for (int n = 0; n < 4; n++) bv[n] = BIAS ? bias[colBase + tx * 4 + n] : 0.0f;

#pragma unroll
    for (int mi = 0; mi < 4; mi++) {
#pragma unroll
        for (int h = 0; h < 2; h++) {
            int r = rowBase + ty * 8 + 2 * mi + h;
            if (r >= M) continue;
            float4 o;
            float* po = (float*)&o;
#pragma unroll
            for (int n = 0; n < 4; n++) {
                float v = ((const float*)&acc2[mi][n])[h] + bv[n];
                if (RELU) v = fmaxf(v, 0.0f);
                po[n] = v;
            }
            *(float4*)&C[(size_t)r * Ncol + colBase + tx * 4] = o;
        }
    }
}

// ---------------- edge dot + double-precision sum / sumsq --------------------
// llp rows: [0:64)=logits, [64:128)=logits@P
__global__ void edge_dot_k(const int* __restrict__ row, const int* __restrict__ col,
                           const float* __restrict__ llp, int E) {
    int e = blockIdx.x * blockDim.x + threadIdx.x;
    float s = 0.0f;
    if (e < E) {
        const float4* a = (const float4*)(llp + (size_t)row[e] * 128);
        const float4* b = (const float4*)(llp + (size_t)col[e] * 128 + 64);
#pragma unroll
        for (int i = 0; i < OUT_DIM / 4; i++) {
            float4 fa = a[i], fb = b[i];
            s += fa.x * fb.x + fa.y * fb.y + fa.z * fb.z + fa.w * fb.w;
        }
        g_ew[e] = s;
    }
    double ds = (e < E) ? (double)s : 0.0;
    double dss = ds * ds;
#pragma unroll
    for (int o = 16; o > 0; o >>= 1) {
        ds += __shfl_down_sync(0xffffffffu, ds, o);
        dss += __shfl_down_sync(0xffffffffu, dss, o);
    }
    __shared__ double sh0[8], sh1[8];
    int w = threadIdx.x >> 5, l = threadIdx.x & 31;
    if (l == 0) { sh0[w] = ds; sh1[w] = dss; }
    __syncthreads();
    if (threadIdx.x == 0) {
        double t0 = 0, t1 = 0;
        int nw = blockDim.x >> 5;
        for (int i = 0; i < nw; i++) { t0 += sh0[i]; t1 += sh1[i]; }
        atomicAdd(&g_stats[0], t0);
        atomicAdd(&g_stats[1], t1);
    }
}

__global__ void finalize_stats_k(int E) {
    double sum = g_stats[0], sumsq = g_stats[1];
    double mean = sum / (double)E;
    double var = (sumsq - sum * sum / (double)E) / (double)(E - 1);
    g_mean = (float)mean;
    g_scale = (float)sqrt(1e-4 / var);
}

__global__ void deg_init_k(int N) {
    int i = blockIdx.x * blockDim.x + threadIdx.x;
    if (i < N) g_deg[i] = 1.0f;   // self-loop weight
}

__global__ void ewn_deg_k(const int* __restrict__ col, int E) {
    int e = blockIdx.x * blockDim.x + threadIdx.x;
    if (e < E) {
        float v = (g_ew[e] - g_mean) * g_scale + 1.0f;
        g_ewn[e] = v;
        atomicAdd(&g_deg[col[e]], v);
    }
}

__global__ void dinv_k(int N) {
    int i = blockIdx.x * blockDim.x + threadIdx.x;
    if (i < N) {
        float d = g_deg[i];
        g_dinv[i] = (d > 0.0f) ? rsqrtf(d) : 0.0f;
    }
}

// agg[i,:] = dinv[i]^2 * hin[i,:]   (self-loop contribution), float4-wide
__global__ void agg_init_k(const float* __restrict__ hin, int N) {
    int i = blockIdx.x * blockDim.x + threadIdx.x;  // over N*32 float4s
    if (i >= N * (H_DIM / 4)) return;
    int node = i / (H_DIM / 4);
    float d = g_dinv[node];
    float c = d * d;
    float4 h = ((const float4*)hin)[i];
    ((float4*)g_agg)[i] = make_float4(c * h.x, c * h.y, c * h.z, c * h.w);
}

// one warp per edge; vector red.global.add (sm_90+) -> 32 reds/edge not 128
__global__ __launch_bounds__(256) void scatter_k(const int* __restrict__ row,
                                                 const int* __restrict__ col,
                                                 const float* __restrict__ hin,
                                                 int E) {
    int warp = (blockIdx.x * blockDim.x + threadIdx.x) >> 5;
    int lane = threadIdx.x & 31;
    if (warp >= E) return;
    int r = row[warp];
    int c = col[warp];
    float coef = g_dinv[r] * g_ewn[warp] * g_dinv[c];
    float4 h = *(const float4*)(hin + (size_t)r * H_DIM + lane * 4);
    float* dst = g_agg + (size_t)c * H_DIM + lane * 4;
    asm volatile("red.global.add.v4.f32 [%0], {%1,%2,%3,%4};" ::"l"(dst),
                 "f"(coef * h.x), "f"(coef * h.y), "f"(coef * h.z),
                 "f"(coef * h.w)
                 : "memory");
}

// -----------------------------------------------------------------------------
extern "C" void kernel_launch(void* const* d_in, const int* in_sizes, int n_in,
                              void* d_out, int out_size) {
    const float* x        = (const float*)d_in[0];
    const int*   eidx     = (const int*)d_in[1];
    const float* mlp_w1   = (const float*)d_in[2];
    const float* mlp_b1   = (const float*)d_in[3];
    const float* mlp_w2   = (const float*)d_in[4];
    const float* mlp_b2   = (const float*)d_in[5];
    const float* mlp_w3   = (const float*)d_in[6];
    const float* mlp_b3   = (const float*)d_in[7];
    const float* parsing  = (const float*)d_in[8];
    const float* lin0_w   = (const float*)d_in[9];
    const float* lin0_b   = (const float*)d_in[10];
    const float* lin1_w   = (const float*)d_in[11];
    const float* lin1_b   = (const float*)d_in[12];
    const float* conv_w1  = (const float*)d_in[13];
    // conv_w2 (d_in[14]) is dead: alpha == 0 kills all x0a terms.

    const int N = in_sizes[0] / IN_DIM;
    const int E = in_sizes[1] / 2;
    const int* erow = eidx;
    const int* ecol = eidx + E;

    float* out = (float*)d_out;

    // resolve scratch addresses (host-side symbol query; not a stream op)
    float *p_h1, *p_llp, *p_lp, *p_x0, *p_agg, *p_hbuf, *p_Weff, *p_Wcat, *p_bcat;
    cudaGetSymbolAddress((void**)&p_h1, g_h1);
    cudaGetSymbolAddress((void**)&p_llp, g_llp);
    cudaGetSymbolAddress((void**)&p_lp, g_lp);
    cudaGetSymbolAddress((void**)&p_x0, g_x0);
    cudaGetSymbolAddress((void**)&p_agg, g_agg);
    cudaGetSymbolAddress((void**)&p_hbuf, g_hbuf);
    cudaGetSymbolAddress((void**)&p_Weff, g_Weff);
    cudaGetSymbolAddress((void**)&p_Wcat, g_Wcat);
    cudaGetSymbolAddress((void**)&p_bcat, g_bcat);

    const int MB = (N + BM - 1) / BM;  // 391 row blocks

    // 0) prep
    prep_k<<<64, 256>>>(parsing, conv_w1);
    prep2_k<<<1, 256>>>(mlp_w3, mlp_b3);

    // 1) MLP: h1 = relu(x@w1+b1); h2 = relu(h1@w2+b2);
    //    llp = h2@[w3 | w3@P] + [b3 | b3@P]   (logits and logits@P in one GEMM)
    sgemm_k<true, true><<<dim3(MB, HID / BN), 256>>>(x, mlp_w1, mlp_b1, p_h1, N, IN_DIM, HID);
    sgemm_k<true, true><<<dim3(MB, 1), 256>>>(p_h1, mlp_w2, mlp_b2, p_lp, N, HID, OUT_DIM);
    sgemm_k<false, true><<<dim3(MB, 2), 256>>>(p_lp, p_Wcat, p_bcat, p_llp, N, OUT_DIM, 128);

    // 2) x0 = relu(x@lin0+b0)
    sgemm_k<true, true><<<dim3(MB, H_DIM / BN), 256>>>(x, lin0_w, lin0_b, p_x0, N, IN_DIM, H_DIM);

    // 3) edge weights + standardization
    edge_dot_k<<<(E + 255) / 256, 256>>>(erow, ecol, p_llp, E);
    finalize_stats_k<<<1, 1>>>(E);
    deg_init_k<<<(N + 255) / 256, 256>>>(N);
    ewn_deg_k<<<(E + 255) / 256, 256>>>(ecol, E);
    dinv_k<<<(N + 255) / 256, 256>>>(N);

    // 4) GCN2 layers (alpha=0 -> out = relu(agg @ Weff[ln]))
    const float* hin = p_x0;
    float* hout = p_hbuf;
    for (int ln = 0; ln < 2; ln++) {
        int nvec = N * (H_DIM / 4);
        agg_init_k<<<(nvec + 255) / 256, 256>>>(hin, N);
        scatter_k<<<(E * 32 + 255) / 256, 256>>>(erow, ecol, hin, E);
        sgemm_k<true, false><<<dim3(MB, H_DIM / BN), 256>>>(
            p_agg, p_Weff + ln * H_DIM * H_DIM, nullptr, hout, N, H_DIM, H_DIM);
        const float* t = hin;
        hin = hout;
        hout = (ln == 0) ? p_x0 : (float*)t;  // ping-pong (x0 dead after layer 0)
    }

    // 5) out = hcur @ lin1 + b  (no relu)
    sgemm_k<false, true><<<dim3(MB, 1), 256>>>(hin, lin1_w, lin1_b, out, N, H_DIM, OUT_DIM);
}